// round 2
// baseline (speedup 1.0000x reference)
#include <cuda_runtime.h>
#include <cuda_bf16.h>
#include <mma.h>
#include <math.h>

using namespace nvcuda;

#define T_TOK 2048
#define H_DIM 2048
#define I_DIM 4096
#define NEXP  8

// ---------------- device scratch (no allocations allowed) ----------------
__device__ __align__(16) float d_xs [T_TOK * H_DIM];        // 16 MB: score-scaled gathered input (grouped by expert)
__device__ __align__(16) float d_gu [T_TOK * 2 * I_DIM];    // 64 MB: routed gate_up output (grouped rows)
__device__ __align__(16) float d_act[T_TOK * I_DIM];        // 32 MB: routed swiglu activation (grouped rows)
__device__ __align__(16) float d_g  [T_TOK * I_DIM];        // 32 MB: shared gate (then reused as shared act)
__device__ __align__(16) float d_u  [T_TOK * I_DIM];        // 32 MB: shared up
__device__ float d_score[T_TOK];
__device__ int   d_eid[T_TOK];
__device__ int   d_order[T_TOK];
__device__ int   d_cnt[NEXP];
__device__ int   d_off[NEXP + 1];
__device__ int   d_cnt2[NEXP];

// ---------------- small kernels ----------------
__global__ void init_kernel() {
    if (threadIdx.x < NEXP) { d_cnt[threadIdx.x] = 0; d_cnt2[threadIdx.x] = 0; }
}

__global__ void router_kernel(const float* __restrict__ x, const float* __restrict__ rw) {
    int t = blockIdx.x;
    const float* xr = x + (size_t)t * H_DIM;
    float acc[NEXP];
#pragma unroll
    for (int e = 0; e < NEXP; e++) acc[e] = 0.f;
    for (int h = threadIdx.x; h < H_DIM; h += blockDim.x) {
        float xv = xr[h];
#pragma unroll
        for (int e = 0; e < NEXP; e++) acc[e] = fmaf(xv, rw[e * H_DIM + h], acc[e]);
    }
    __shared__ float red[8][NEXP];
    int lane = threadIdx.x & 31, w = threadIdx.x >> 5;
#pragma unroll
    for (int e = 0; e < NEXP; e++) {
        float v = acc[e];
#pragma unroll
        for (int o = 16; o > 0; o >>= 1) v += __shfl_down_sync(0xffffffffu, v, o);
        if (lane == 0) red[w][e] = v;
    }
    __syncthreads();
    if (threadIdx.x == 0) {
        float best = -1e30f; int bi = 0;
#pragma unroll
        for (int e = 0; e < NEXP; e++) {
            float v = 0.f;
#pragma unroll
            for (int w2 = 0; w2 < 8; w2++) v += red[w2][e];
            if (v > best) { best = v; bi = e; }
        }
        d_eid[t] = bi;
        d_score[t] = 1.f / (1.f + expf(-best));
        atomicAdd(&d_cnt[bi], 1);
    }
}

__global__ void offsets_kernel() {
    if (threadIdx.x == 0) {
        int s = 0;
        for (int e = 0; e < NEXP; e++) { d_off[e] = s; s += d_cnt[e]; }
        d_off[NEXP] = s;
    }
}

__global__ void gather_kernel(const float* __restrict__ x) {
    int t = blockIdx.x;
    __shared__ int spos; __shared__ float ss;
    if (threadIdx.x == 0) {
        int e = d_eid[t];
        int p = atomicAdd(&d_cnt2[e], 1) + d_off[e];
        d_order[p] = t; spos = p; ss = d_score[t];
    }
    __syncthreads();
    int p = spos; float s = ss;
    const float4* src = (const float4*)(x + (size_t)t * H_DIM);
    float4* dst = (float4*)(d_xs + (size_t)p * H_DIM);
    for (int i = threadIdx.x; i < H_DIM / 4; i += blockDim.x) {
        float4 v = src[i];
        v.x *= s; v.y *= s; v.z *= s; v.w *= s;
        dst[i] = v;
    }
}

__device__ __forceinline__ float silu_f(float g) { return g / (1.f + expf(-g)); }

__global__ void swiglu_routed_kernel() {
    int idx = blockIdx.x * blockDim.x + threadIdx.x;
    const int total4 = T_TOK * I_DIM / 4;
    if (idx >= total4) return;
    int row = idx / (I_DIM / 4);
    int c4  = idx % (I_DIM / 4);
    const float4* gp = (const float4*)(d_gu + (size_t)row * 2 * I_DIM);
    float4 g = gp[c4];
    float4 u = gp[c4 + I_DIM / 4];
    float4 r;
    r.x = u.x * silu_f(g.x);
    r.y = u.y * silu_f(g.y);
    r.z = u.z * silu_f(g.z);
    r.w = u.w * silu_f(g.w);
    ((float4*)d_act)[idx] = r;
}

__global__ void swiglu_shared_kernel() {
    int idx = blockIdx.x * blockDim.x + threadIdx.x;
    const int total4 = T_TOK * I_DIM / 4;
    if (idx >= total4) return;
    float4 g = ((const float4*)d_g)[idx];
    float4 u = ((const float4*)d_u)[idx];
    float4 r;
    r.x = u.x * silu_f(g.x);
    r.y = u.y * silu_f(g.y);
    r.z = u.z * silu_f(g.z);
    r.w = u.w * silu_f(g.w);
    ((float4*)d_g)[idx] = r;
}

// ---------------- generic tf32 wmma GEMM ----------------
// C[M,N] (+)= A[M,K] * B[K,N], all row-major fp32 in gmem, tf32 tensor compute.
// expert_mode: blockIdx.x = e*16 + mblk; rows for expert e are d_cnt[e] starting
// at grouped row d_off[e]; B += e*bStride. remap: C row = d_order[off+local].
#define BM 128
#define BN 128
#define BK 32
#define AS_LD 36
#define BS_LD 132

__global__ __launch_bounds__(256, 2)
void gemm_tf32(const float* __restrict__ A, int lda,
               const float* __restrict__ B, int ldb, long long bStride,
               float* __restrict__ C, int ldc,
               int M, int N, int K,
               int expert_mode, int remap, int accumulate)
{
    __shared__ float As[BM][AS_LD];
    __shared__ float Bs[BK][BS_LD];
    __shared__ float stage[8][16 * 20];

    int mblk = blockIdx.x;
    const int* rowmap = nullptr;
    int row_base = 0;
    int Mloc = M;
    if (expert_mode) {
        const int mbPerE = (T_TOK + BM - 1) / BM;  // 16
        int e = blockIdx.x / mbPerE;
        mblk = blockIdx.x % mbPerE;
        Mloc = d_cnt[e];
        if (mblk * BM >= Mloc) return;
        A += (size_t)d_off[e] * lda;
        B += (size_t)e * bStride;
        if (remap) rowmap = d_order + d_off[e];
        else       row_base = d_off[e];
    }
    const int row0 = mblk * BM;
    const int n0 = blockIdx.y * BN;
    const int tid = threadIdx.x;
    const int warp = tid >> 5;
    const int wm = warp & 3;   // 4 warps along M (32 rows each)
    const int wn = warp >> 2;  // 2 warps along N (64 cols each)

    wmma::fragment<wmma::accumulator, 16, 16, 8, float> c[2][4];
#pragma unroll
    for (int mi = 0; mi < 2; mi++)
#pragma unroll
        for (int ni = 0; ni < 4; ni++)
            wmma::fill_fragment(c[mi][ni], 0.f);

    for (int k0 = 0; k0 < K; k0 += BK) {
        // load A tile [BM x BK]
#pragma unroll
        for (int i = 0; i < 4; i++) {
            int r  = (tid >> 3) + i * 32;
            int c4 = (tid & 7) * 4;
            float4 v = make_float4(0.f, 0.f, 0.f, 0.f);
            if (row0 + r < Mloc)
                v = *(const float4*)(A + (size_t)(row0 + r) * lda + k0 + c4);
            *(float4*)(&As[r][c4]) = v;
        }
        // load B tile [BK x BN]
#pragma unroll
        for (int i = 0; i < 4; i++) {
            int r  = (tid >> 5) + i * 8;
            int c4 = (tid & 31) * 4;
            float4 v = *(const float4*)(B + (size_t)(k0 + r) * ldb + n0 + c4);
            *(float4*)(&Bs[r][c4]) = v;
        }
        __syncthreads();
#pragma unroll
        for (int kk = 0; kk < BK / 8; kk++) {
            wmma::fragment<wmma::matrix_a, 16, 16, 8, wmma::precision::tf32, wmma::row_major> a[2];
            wmma::fragment<wmma::matrix_b, 16, 16, 8, wmma::precision::tf32, wmma::row_major> b[4];
#pragma unroll
            for (int mi = 0; mi < 2; mi++) {
                wmma::load_matrix_sync(a[mi], &As[wm * 32 + mi * 16][kk * 8], AS_LD);
#pragma unroll
                for (int el = 0; el < a[mi].num_elements; el++)
                    a[mi].x[el] = wmma::__float_to_tf32(a[mi].x[el]);
            }
#pragma unroll
            for (int ni = 0; ni < 4; ni++) {
                wmma::load_matrix_sync(b[ni], &Bs[kk * 8][wn * 64 + ni * 16], BS_LD);
#pragma unroll
                for (int el = 0; el < b[ni].num_elements; el++)
                    b[ni].x[el] = wmma::__float_to_tf32(b[ni].x[el]);
            }
#pragma unroll
            for (int mi = 0; mi < 2; mi++)
#pragma unroll
                for (int ni = 0; ni < 4; ni++)
                    wmma::mma_sync(c[mi][ni], a[mi], b[ni], c[mi][ni]);
        }
        __syncthreads();
    }

    // epilogue: stage per-warp in smem, then (optionally remapped / accumulated) global write
    const int lane = tid & 31;
#pragma unroll
    for (int mi = 0; mi < 2; mi++) {
#pragma unroll
        for (int ni = 0; ni < 4; ni++) {
            wmma::store_matrix_sync(&stage[warp][0], c[mi][ni], 20, wmma::mem_row_major);
            __syncwarp();
#pragma unroll
            for (int j = 0; j < 8; j++) {
                int idx = lane * 8 + j;        // 0..255
                int r = idx >> 4, cc = idx & 15;
                int gloc = row0 + wm * 32 + mi * 16 + r;
                if (gloc < Mloc) {
                    int grow = rowmap ? rowmap[gloc] : (row_base + gloc);
                    int gcol = n0 + wn * 64 + ni * 16 + cc;
                    float v = stage[warp][r * 20 + cc];
                    float* p = C + (size_t)grow * ldc + gcol;
                    if (accumulate) *p += v; else *p = v;
                }
            }
            __syncwarp();
        }
    }
}

// ---------------- launch ----------------
extern "C" void kernel_launch(void* const* d_in, const int* in_sizes, int n_in,
                              void* d_out, int out_size)
{
    const float* x   = (const float*)d_in[0];   // [T, H]
    const float* rw  = (const float*)d_in[1];   // [E, H]
    const float* gup = (const float*)d_in[2];   // [E, H, 2I]
    const float* dwn = (const float*)d_in[3];   // [E, I, H]
    const float* sg  = (const float*)d_in[4];   // [H, I]
    const float* su  = (const float*)d_in[5];   // [H, I]
    const float* sd  = (const float*)d_in[6];   // [I, H]
    float* out = (float*)d_out;                  // [T, H]

    void *p_xs, *p_gu, *p_act, *p_g, *p_u;
    cudaGetSymbolAddress(&p_xs,  d_xs);
    cudaGetSymbolAddress(&p_gu,  d_gu);
    cudaGetSymbolAddress(&p_act, d_act);
    cudaGetSymbolAddress(&p_g,   d_g);
    cudaGetSymbolAddress(&p_u,   d_u);

    // 1) routing
    init_kernel<<<1, 32>>>();
    router_kernel<<<T_TOK, 256>>>(x, rw);
    offsets_kernel<<<1, 1>>>();
    gather_kernel<<<T_TOK, 256>>>(x);

    const int sw_blocks = (T_TOK * I_DIM / 4 + 255) / 256;

    // 2) shared expert: gate, up, swiglu, down(out =)
    gemm_tf32<<<dim3(T_TOK / BM, I_DIM / BN), 256>>>(
        x, H_DIM, sg, I_DIM, 0, (float*)p_g, I_DIM, T_TOK, I_DIM, H_DIM, 0, 0, 0);
    gemm_tf32<<<dim3(T_TOK / BM, I_DIM / BN), 256>>>(
        x, H_DIM, su, I_DIM, 0, (float*)p_u, I_DIM, T_TOK, I_DIM, H_DIM, 0, 0, 0);
    swiglu_shared_kernel<<<sw_blocks, 256>>>();
    gemm_tf32<<<dim3(T_TOK / BM, H_DIM / BN), 256>>>(
        (const float*)p_g, I_DIM, sd, H_DIM, 0, out, H_DIM, T_TOK, H_DIM, I_DIM, 0, 0, 0);

    // 3) routed experts (grouped rows): gate_up, swiglu, down(out +=, scattered)
    gemm_tf32<<<dim3(NEXP * (T_TOK / BM), 2 * I_DIM / BN), 256>>>(
        (const float*)p_xs, H_DIM, gup, 2 * I_DIM, (long long)H_DIM * 2 * I_DIM,
        (float*)p_gu, 2 * I_DIM, T_TOK, 2 * I_DIM, H_DIM, 1, 0, 0);
    swiglu_routed_kernel<<<sw_blocks, 256>>>();
    gemm_tf32<<<dim3(NEXP * (T_TOK / BM), H_DIM / BN), 256>>>(
        (const float*)p_act, I_DIM, dwn, H_DIM, (long long)I_DIM * H_DIM,
        out, H_DIM, T_TOK, H_DIM, I_DIM, 1, 1, 1);
}

// round 4
// speedup vs baseline: 2.0044x; 2.0044x over previous
#include <cuda_runtime.h>
#include <stdint.h>
#include <math.h>

#define T_TOK 2048
#define H_DIM 2048
#define I_DIM 4096
#define NEXP  8

// ---------------- device scratch ----------------
__device__ __align__(16) float d_xq [T_TOK * H_DIM];
__device__ __align__(16) float d_xs [T_TOK * H_DIM];
__device__ __align__(16) float d_gu [(size_t)T_TOK * 2 * I_DIM];
__device__ __align__(16) float d_act[T_TOK * I_DIM];
__device__ __align__(16) float d_g  [T_TOK * I_DIM];
__device__ __align__(16) float d_u  [T_TOK * I_DIM];
__device__ float d_score[T_TOK];
__device__ int   d_eid[T_TOK];
__device__ int   d_order[T_TOK];
__device__ int   d_cnt[NEXP];
__device__ int   d_off[NEXP + 1];
__device__ int   d_cnt2[NEXP];

// ---------------- helpers ----------------
__device__ __forceinline__ uint32_t smem_u32(const void* p) {
    uint32_t a;
    asm("{ .reg .u64 t; cvta.to.shared.u64 t, %1; cvt.u32.u64 %0, t; }" : "=r"(a) : "l"(p));
    return a;
}
__device__ __forceinline__ float rn_tf32(float v) {
    uint32_t r;
    asm("cvt.rna.tf32.f32 %0, %1;" : "=r"(r) : "f"(v));
    return __uint_as_float(r);
}
__device__ __forceinline__ uint32_t f2tf32u(float v) {
    uint32_t r;
    asm("cvt.rna.tf32.f32 %0, %1;" : "=r"(r) : "f"(v));
    return r;
}
__device__ __forceinline__ void cpasync16(uint32_t s, const float* g) {
    asm volatile("cp.async.cg.shared.global [%0], [%1], 16;" :: "r"(s), "l"(g) : "memory");
}
__device__ __forceinline__ void ldsm_x4(uint32_t* r, uint32_t addr) {
    asm volatile("ldmatrix.sync.aligned.m8n8.x4.shared.b16 {%0,%1,%2,%3}, [%4];"
                 : "=r"(r[0]), "=r"(r[1]), "=r"(r[2]), "=r"(r[3]) : "r"(addr));
}
__device__ __forceinline__ void mma8(float* d, const uint32_t* a, const uint32_t* b) {
    asm volatile(
        "mma.sync.aligned.m16n8k8.row.col.f32.tf32.tf32.f32 "
        "{%0,%1,%2,%3}, {%4,%5,%6,%7}, {%8,%9}, {%0,%1,%2,%3};"
        : "+f"(d[0]), "+f"(d[1]), "+f"(d[2]), "+f"(d[3])
        : "r"(a[0]), "r"(a[1]), "r"(a[2]), "r"(a[3]), "r"(b[0]), "r"(b[1]));
}

// ---------------- small kernels ----------------
__global__ void init_kernel() {
    if (threadIdx.x < NEXP) { d_cnt[threadIdx.x] = 0; d_cnt2[threadIdx.x] = 0; }
}

__global__ void router_kernel(const float* __restrict__ x, const float* __restrict__ rw) {
    int t = blockIdx.x;
    const float* xr = x + (size_t)t * H_DIM;
    float acc[NEXP];
#pragma unroll
    for (int e = 0; e < NEXP; e++) acc[e] = 0.f;
    for (int h = threadIdx.x; h < H_DIM; h += blockDim.x) {
        float xv = xr[h];
#pragma unroll
        for (int e = 0; e < NEXP; e++) acc[e] = fmaf(xv, rw[e * H_DIM + h], acc[e]);
    }
    __shared__ float red[8][NEXP];
    int lane = threadIdx.x & 31, w = threadIdx.x >> 5;
#pragma unroll
    for (int e = 0; e < NEXP; e++) {
        float v = acc[e];
#pragma unroll
        for (int o = 16; o > 0; o >>= 1) v += __shfl_down_sync(0xffffffffu, v, o);
        if (lane == 0) red[w][e] = v;
    }
    __syncthreads();
    if (threadIdx.x == 0) {
        float best = -1e30f; int bi = 0;
#pragma unroll
        for (int e = 0; e < NEXP; e++) {
            float v = 0.f;
#pragma unroll
            for (int w2 = 0; w2 < 8; w2++) v += red[w2][e];
            if (v > best) { best = v; bi = e; }
        }
        d_eid[t] = bi;
        d_score[t] = 1.f / (1.f + expf(-best));
        atomicAdd(&d_cnt[bi], 1);
    }
}

__global__ void offsets_kernel() {
    if (threadIdx.x == 0) {
        int s = 0;
        for (int e = 0; e < NEXP; e++) { d_off[e] = s; s += d_cnt[e]; }
        d_off[NEXP] = s;
    }
}

__global__ void gather_kernel(const float* __restrict__ x) {
    int t = blockIdx.x;
    __shared__ int spos; __shared__ float ss;
    if (threadIdx.x == 0) {
        int e = d_eid[t];
        int p = atomicAdd(&d_cnt2[e], 1) + d_off[e];
        d_order[p] = t; spos = p; ss = d_score[t];
    }
    __syncthreads();
    int p = spos; float s = ss;
    const float4* src = (const float4*)(x + (size_t)t * H_DIM);
    float4* dst = (float4*)(d_xs + (size_t)p * H_DIM);
    for (int i = threadIdx.x; i < H_DIM / 4; i += blockDim.x) {
        float4 v = src[i];
        v.x = rn_tf32(v.x * s); v.y = rn_tf32(v.y * s);
        v.z = rn_tf32(v.z * s); v.w = rn_tf32(v.w * s);
        dst[i] = v;
    }
}

__global__ void round_x_kernel(const float* __restrict__ x) {
    int i = blockIdx.x * blockDim.x + threadIdx.x;
    if (i >= T_TOK * H_DIM / 4) return;
    float4 v = ((const float4*)x)[i];
    v.x = rn_tf32(v.x); v.y = rn_tf32(v.y); v.z = rn_tf32(v.z); v.w = rn_tf32(v.w);
    ((float4*)d_xq)[i] = v;
}

__device__ __forceinline__ float silu_f(float g) { return g / (1.f + expf(-g)); }

__global__ void swiglu_routed_kernel() {
    int idx = blockIdx.x * blockDim.x + threadIdx.x;
    const int total4 = T_TOK * I_DIM / 4;
    if (idx >= total4) return;
    int row = idx / (I_DIM / 4);
    int c4  = idx % (I_DIM / 4);
    const float4* gp = (const float4*)(d_gu + (size_t)row * 2 * I_DIM);
    float4 g = gp[c4];
    float4 u = gp[c4 + I_DIM / 4];
    float4 r;
    r.x = rn_tf32(u.x * silu_f(g.x));
    r.y = rn_tf32(u.y * silu_f(g.y));
    r.z = rn_tf32(u.z * silu_f(g.z));
    r.w = rn_tf32(u.w * silu_f(g.w));
    ((float4*)d_act)[idx] = r;
}

__global__ void swiglu_shared_kernel() {
    int idx = blockIdx.x * blockDim.x + threadIdx.x;
    const int total4 = T_TOK * I_DIM / 4;
    if (idx >= total4) return;
    float4 g = ((const float4*)d_g)[idx];
    float4 u = ((const float4*)d_u)[idx];
    float4 r;
    r.x = rn_tf32(u.x * silu_f(g.x));
    r.y = rn_tf32(u.y * silu_f(g.y));
    r.z = rn_tf32(u.z * silu_f(g.z));
    r.w = rn_tf32(u.w * silu_f(g.w));
    ((float4*)d_g)[idx] = r;
}

// ---------------- mma.sync tf32 GEMM, cp.async 4-stage ----------------
// C[*,N](+)= A[M,K]·B[K,N]; tile 128x128x32; A pre-rounded tf32, B rounded on load.
#define STAGES     4
#define A_FLOATS   (128 * 36)       // 36-float pitch
#define B_FLOATS   (32 * 136)       // 136-float pitch
#define STG_FLOATS (A_FLOATS + B_FLOATS)
#define STG_BYTES  (STG_FLOATS * 4) // 35840
#define GSMEM      (STAGES * STG_BYTES)

__global__ __launch_bounds__(256, 1)
void gemm_mma(const float* __restrict__ A, int lda,
              const float* __restrict__ B, int ldb, long long bStride,
              float* __restrict__ C, int ldc, int K,
              int expert_mode, int remap, int accumulate)
{
    extern __shared__ float sm[];
    const int tid = threadIdx.x, lane = tid & 31, warp = tid >> 5;
    const int n0 = blockIdx.y * 128;
    int rowA0, Mvalid = 128;
    const int* rowmap = nullptr;
    if (expert_mode) {
        int e = blockIdx.x >> 4, mb = blockIdx.x & 15;
        int cnt = d_cnt[e];
        if (mb * 128 >= cnt) return;
        rowA0 = d_off[e] + mb * 128;
        Mvalid = min(128, cnt - mb * 128);
        B += (size_t)e * bStride;
        if (remap) rowmap = d_order + rowA0;
    } else {
        rowA0 = blockIdx.x * 128;
    }

    const uint32_t smb = smem_u32(sm);
    const int nK = K >> 5;
    const int mclamp = Mvalid - 1;

    // ---- stage loader ----
    auto load_stage = [&](int slot, int ksIdx) {
        int k0 = ksIdx * 32;
        uint32_t sA = smb + slot * STG_BYTES;
        uint32_t sB = sA + A_FLOATS * 4;
#pragma unroll
        for (int j = 0; j < 4; j++) {
            int idx = tid + 256 * j;
            int r = idx >> 3, c = idx & 7;
            int rc = min(r, mclamp);
            cpasync16(sA + r * 144 + c * 16,
                      A + (size_t)(rowA0 + rc) * lda + k0 + c * 4);
        }
#pragma unroll
        for (int j = 0; j < 4; j++) {
            int idx = tid + 256 * j;
            int r = idx >> 5, c = idx & 31;
            cpasync16(sB + r * 544 + c * 16,
                      B + (size_t)(k0 + r) * ldb + n0 + c * 4);
        }
    };

#pragma unroll
    for (int s = 0; s < 3; s++) {
        load_stage(s, s);
        asm volatile("cp.async.commit_group;" ::: "memory");
    }

    const int wm = warp & 3, wn = warp >> 2;
    const int mat = lane >> 3;
    const uint32_t aOff = (uint32_t)((wm * 32 + (mat & 1) * 8 + (lane & 7)) * 144 + (mat >> 1) * 16);
    const int bOff = (lane & 3) * 136 + wn * 64 + (lane >> 2);

    float d[2][8][4];
#pragma unroll
    for (int mt = 0; mt < 2; mt++)
#pragma unroll
        for (int nt = 0; nt < 8; nt++)
#pragma unroll
            for (int q = 0; q < 4; q++) d[mt][nt][q] = 0.f;

#pragma unroll 1
    for (int ks = 0; ks < nK; ks++) {
        asm volatile("cp.async.wait_group 2;" ::: "memory");
        __syncthreads();
        int t = ks + 3;
        if (t < nK) load_stage(t & 3, t);
        asm volatile("cp.async.commit_group;" ::: "memory");

        const int slot = ks & 3;
        const uint32_t aBase = smb + slot * STG_BYTES + aOff;
        const float* Bs = sm + slot * STG_FLOATS + A_FLOATS + bOff;

        uint32_t a[2][2][4];
        uint32_t b[2][8][2];
        ldsm_x4(a[0][0], aBase);
        ldsm_x4(a[0][1], aBase + 2304);
#pragma unroll
        for (int nt = 0; nt < 8; nt++) {
            b[0][nt][0] = f2tf32u(Bs[nt * 8]);
            b[0][nt][1] = f2tf32u(Bs[nt * 8 + 544]);
        }
#pragma unroll
        for (int kk = 0; kk < 4; kk++) {
            int cur = kk & 1, nxt = cur ^ 1;
            if (kk < 3) {
                ldsm_x4(a[nxt][0], aBase + (kk + 1) * 32);
                ldsm_x4(a[nxt][1], aBase + 2304 + (kk + 1) * 32);
                const float* Bk = Bs + (kk + 1) * 1088;
#pragma unroll
                for (int nt = 0; nt < 8; nt++) {
                    b[nxt][nt][0] = f2tf32u(Bk[nt * 8]);
                    b[nxt][nt][1] = f2tf32u(Bk[nt * 8 + 544]);
                }
            }
#pragma unroll
            for (int mt = 0; mt < 2; mt++)
#pragma unroll
                for (int nt = 0; nt < 8; nt++)
                    mma8(d[mt][nt], a[cur][mt], b[cur][nt]);
        }
    }

    // ---- epilogue: direct register -> gmem ----
    const int g = lane >> 2, c2 = (lane & 3) * 2;
#pragma unroll
    for (int mt = 0; mt < 2; mt++) {
#pragma unroll
        for (int half = 0; half < 2; half++) {
            int rl = wm * 32 + mt * 16 + half * 8 + g;
            if (rl < Mvalid) {
                int grow = rowmap ? rowmap[rl] : (rowA0 + rl);
                float* cp0 = C + (size_t)grow * ldc + n0 + wn * 64 + c2;
#pragma unroll
                for (int nt = 0; nt < 8; nt++) {
                    float2 v;
                    v.x = d[mt][nt][half * 2];
                    v.y = d[mt][nt][half * 2 + 1];
                    float2* p = (float2*)(cp0 + nt * 8);
                    if (accumulate) { float2 o = *p; v.x += o.x; v.y += o.y; }
                    *p = v;
                }
            }
        }
    }
}

// ---------------- host ----------------
extern "C" void kernel_launch(void* const* d_in, const int* in_sizes, int n_in,
                              void* d_out, int out_size)
{
    const float* x   = (const float*)d_in[0];
    const float* rw  = (const float*)d_in[1];
    const float* gup = (const float*)d_in[2];
    const float* dwn = (const float*)d_in[3];
    const float* sg  = (const float*)d_in[4];
    const float* su  = (const float*)d_in[5];
    const float* sd  = (const float*)d_in[6];
    float* out = (float*)d_out;

    void *p_xq, *p_xs, *p_gu, *p_act, *p_g, *p_u;
    cudaGetSymbolAddress(&p_xq, d_xq);   cudaGetSymbolAddress(&p_xs, d_xs);
    cudaGetSymbolAddress(&p_gu, d_gu);   cudaGetSymbolAddress(&p_act, d_act);
    cudaGetSymbolAddress(&p_g, d_g);     cudaGetSymbolAddress(&p_u, d_u);

    cudaFuncSetAttribute(gemm_mma, cudaFuncAttributeMaxDynamicSharedMemorySize, GSMEM);

    // 1) routing + tf32 rounding of activations
    init_kernel<<<1, 32>>>();
    router_kernel<<<T_TOK, 256>>>(x, rw);
    offsets_kernel<<<1, 1>>>();
    gather_kernel<<<T_TOK, 256>>>(x);
    round_x_kernel<<<(T_TOK * H_DIM / 4 + 255) / 256, 256>>>(x);

    const int sw_blocks = (T_TOK * I_DIM / 4 + 255) / 256;

    // 2) shared expert
    gemm_mma<<<dim3(16, I_DIM / 128), 256, GSMEM>>>(
        (const float*)p_xq, H_DIM, sg, I_DIM, 0, (float*)p_g, I_DIM, H_DIM, 0, 0, 0);
    gemm_mma<<<dim3(16, I_DIM / 128), 256, GSMEM>>>(
        (const float*)p_xq, H_DIM, su, I_DIM, 0, (float*)p_u, I_DIM, H_DIM, 0, 0, 0);
    swiglu_shared_kernel<<<sw_blocks, 256>>>();
    gemm_mma<<<dim3(16, H_DIM / 128), 256, GSMEM>>>(
        (const float*)p_g, I_DIM, sd, H_DIM, 0, out, H_DIM, I_DIM, 0, 0, 0);

    // 3) routed experts (grouped rows)
    gemm_mma<<<dim3(NEXP * 16, 2 * I_DIM / 128), 256, GSMEM>>>(
        (const float*)p_xs, H_DIM, gup, 2 * I_DIM, (long long)H_DIM * 2 * I_DIM,
        (float*)p_gu, 2 * I_DIM, H_DIM, 1, 0, 0);
    swiglu_routed_kernel<<<sw_blocks, 256>>>();
    gemm_mma<<<dim3(NEXP * 16, H_DIM / 128), 256, GSMEM>>>(
        (const float*)p_act, I_DIM, dwn, H_DIM, (long long)I_DIM * H_DIM,
        out, H_DIM, I_DIM, 1, 1, 1);
}